// round 1
// baseline (speedup 1.0000x reference)
#include <cuda_runtime.h>
#include <cuda_bf16.h>

// Soft local histogram, R=5, bandwidth=0.5.
// Input/output: (4, 8, 3, 256, 256) fp32 -> treated as 96 images of 256x256.
// out[y,x] = sum_{di,dj in [-2,2]} max(0, 1 - |x[y+di,x+dj] - x[y,x]| / 0.5)
// for y,x in [2, 254); zero on the 2-pixel border.

#define IMG_H 256
#define IMG_W 256
#define TX 32
#define TY 8
#define HALO 2
#define TILE_W (TX + 2 * HALO)   // 36
#define TILE_H (TY + 2 * HALO)   // 12

__global__ __launch_bounds__(TX * TY) void soft_hist_kernel(
    const float* __restrict__ in, float* __restrict__ out)
{
    __shared__ float tile[TILE_H][TILE_W];

    const int img = blockIdx.z;
    const float* im = in + (size_t)img * IMG_H * IMG_W;
    float* om = out + (size_t)img * IMG_H * IMG_W;

    const int x0 = blockIdx.x * TX;
    const int y0 = blockIdx.y * TY;
    const int tx = threadIdx.x;
    const int ty = threadIdx.y;
    const int tid = ty * TX + tx;

    // Cooperative halo load with index clamping. Clamped (out-of-image) values
    // only ever feed outputs in the zero border, which are overwritten with 0,
    // so clamping is safe and avoids OOB reads.
    #pragma unroll
    for (int idx = tid; idx < TILE_H * TILE_W; idx += TX * TY) {
        int ly = idx / TILE_W;
        int lx = idx - ly * TILE_W;
        int gy = y0 + ly - HALO;
        int gx = x0 + lx - HALO;
        gy = min(max(gy, 0), IMG_H - 1);
        gx = min(max(gx, 0), IMG_W - 1);
        tile[ly][lx] = __ldg(&im[gy * IMG_W + gx]);
    }
    __syncthreads();

    const int gx = x0 + tx;
    const int gy = y0 + ty;

    float r = 0.0f;
    if (gx >= HALO && gx < IMG_W - HALO && gy >= HALO && gy < IMG_H - HALO) {
        const float c = tile[ty + HALO][tx + HALO];
        #pragma unroll
        for (int i = 0; i < 5; i++) {
            #pragma unroll
            for (int j = 0; j < 5; j++) {
                float d = fabsf(tile[ty + i][tx + j] - c);
                r += fmaxf(0.0f, 1.0f - 2.0f * d);  // 1/bandwidth = 2
            }
        }
    }
    om[gy * IMG_W + gx] = r;
}

extern "C" void kernel_launch(void* const* d_in, const int* in_sizes, int n_in,
                              void* d_out, int out_size) {
    const float* in = (const float*)d_in[0];
    float* out = (float*)d_out;
    // 4*8*3 = 96 images of 256x256
    dim3 block(TX, TY, 1);
    dim3 grid(IMG_W / TX, IMG_H / TY, 96);
    soft_hist_kernel<<<grid, block>>>(in, out);
}

// round 3
// speedup vs baseline: 1.3394x; 1.3394x over previous
#include <cuda_runtime.h>
#include <cuda_bf16.h>

// Soft local histogram, R=5, bandwidth=0.5.
// Input/output: (4, 8, 3, 256, 256) fp32 -> 96 images of 256x256.
// out[y,x] = sum_{di,dj in [-2,2]} max(0, 1 - 2*|x[y+di,x+dj] - x[y,x]|)
// for y,x in [2, 254); zero on the 2-pixel border.
//
// Strategy: column register blocking (each thread computes PY=8 outputs in a
// vertical column), tap math structured to hit FFMA-imm (rt=1) on the fma pipe
// with abs/relu folded onto the alu pipe (FADD |.| modifier + FMNMX):
//   d   = fmaf(a, 2.0f, -2c)        // FFMA-imm
//   w   = fmaxf(1.0f - |d|, 0.0f)   // FADD(imm,-|d|) + FMNMX (alu pipe)
//   acc = fmaf(w, 2.0f, acc)        // FFMA-imm; acc = 2*sum, halved at end
// Center tap (w == 1) is skipped; acc initialized to 2.0.

#define IMG_H 256
#define IMG_W 256
#define TX 32
#define TYB 4
#define PY 8
#define BH (TYB * PY)            // 32 output rows per block
#define HALO 2
#define TILE_W (TX + 2 * HALO)   // 36
#define TILE_H (BH + 2 * HALO)   // 36

__global__ __launch_bounds__(TX * TYB) void soft_hist_kernel(
    const float* __restrict__ in, float* __restrict__ out)
{
    __shared__ float tile[TILE_H][TILE_W];

    const int img = blockIdx.z;
    const float* im = in + (size_t)img * IMG_H * IMG_W;
    float* om = out + (size_t)img * IMG_H * IMG_W;

    const int x0 = blockIdx.x * TX;
    const int y0 = blockIdx.y * BH;
    const int tx = threadIdx.x;
    const int ty = threadIdx.y;
    const int tid = ty * TX + tx;

    // Cooperative halo load with clamped indices. Clamped values only feed
    // outputs in the forced-zero border, so clamping is safe.
    #pragma unroll
    for (int idx = tid; idx < TILE_H * TILE_W; idx += TX * TYB) {
        int ly = idx / TILE_W;
        int lx = idx - ly * TILE_W;
        int gy = min(max(y0 + ly - HALO, 0), IMG_H - 1);
        int gx = min(max(x0 + lx - HALO, 0), IMG_W - 1);
        tile[ly][lx] = __ldg(&im[gy * IMG_W + gx]);
    }
    __syncthreads();

    // Thread computes outputs at column gx = x0+tx, rows y0 + ty*PY + k.
    // Output k: center = tile[rbase+k+2][tx+2], taps rows rbase+k..rbase+k+4.
    const int rbase = ty * PY;

    float nc2[PY];   // -2 * center
    float acc[PY];   // 2 * running sum
    #pragma unroll
    for (int k = 0; k < PY; k++) {
        nc2[k] = -2.0f * tile[rbase + k + 2][tx + 2];
        acc[k] = 2.0f;   // center tap contributes weight 1 (x2 scaling)
    }

    // Slide over the PY+4 tap rows; each row's 5 values feed up to 5 outputs.
    #pragma unroll
    for (int ry = 0; ry < PY + 4; ry++) {
        float a[5];
        #pragma unroll
        for (int j = 0; j < 5; j++) a[j] = tile[rbase + ry][tx + j];

        #pragma unroll
        for (int k = 0; k < PY; k++) {
            if (ry >= k && ry <= k + 4) {
                #pragma unroll
                for (int j = 0; j < 5; j++) {
                    if (ry == k + 2 && j == 2) continue;  // center: skipped
                    float d = fmaf(a[j], 2.0f, nc2[k]);        // 2(a - c)
                    float w = fmaxf(1.0f - fabsf(d), 0.0f);    // relu(1-2|a-c|)
                    acc[k] = fmaf(w, 2.0f, acc[k]);            // acc += 2w
                }
            }
        }
    }

    const int gx = x0 + tx;
    const bool xin = (gx >= HALO) && (gx < IMG_W - HALO);
    #pragma unroll
    for (int k = 0; k < PY; k++) {
        int gy = y0 + rbase + k;
        bool yin = (gy >= HALO) && (gy < IMG_H - HALO);
        om[gy * IMG_W + gx] = (xin && yin) ? 0.5f * acc[k] : 0.0f;
    }
}

extern "C" void kernel_launch(void* const* d_in, const int* in_sizes, int n_in,
                              void* d_out, int out_size) {
    const float* in = (const float*)d_in[0];
    float* out = (float*)d_out;
    dim3 block(TX, TYB, 1);
    dim3 grid(IMG_W / TX, IMG_H / BH, 96);   // 8 x 8 x 96
    soft_hist_kernel<<<grid, block>>>(in, out);
}

// round 4
// speedup vs baseline: 1.4182x; 1.0588x over previous
#include <cuda_runtime.h>
#include <cuda_bf16.h>

// Soft local histogram, R=5, bandwidth=0.5.
// Input/output: (4, 8, 3, 256, 256) fp32 -> 96 images of 256x256.
// out[y,x] = sum_{di,dj in [-2,2]} max(0, 1 - 2*|x[y+di,x+dj] - x[y,x]|)
// for y,x in [2, 254); zero on the 2-pixel border.
//
// Issue-bound kernel: ~4 instr/tap (FFMA-imm, FADD, FMNMX, FFMA-imm) x 24 taps.
// This round: float4 halo loads with per-block clamped aligned base (kills the
// alu-pipe addressing overhead) + 64-reg budget for LDS latency scheduling.

#define IMG_H 256
#define IMG_W 256
#define TX 32
#define TYB 8
#define PY 8
#define BH (TYB * PY)          // 64 output rows per block
#define TILE_H (BH + 4)        // 68
#define TILE_W 56              // padded row width in floats (covers worst xoff)
#define NF4 12                 // float4s loaded per row (48 floats)
#define NLOAD (TILE_H * NF4)   // 816

__global__ __launch_bounds__(TX * TYB, 4) void soft_hist_kernel(
    const float* __restrict__ in, float* __restrict__ out)
{
    __shared__ float tile[TILE_H][TILE_W];

    const int img = blockIdx.z;
    const float* im = in + (size_t)img * IMG_H * IMG_W;
    float* om = out + (size_t)img * IMG_H * IMG_W;

    const int x0 = blockIdx.x * TX;
    const int y0 = blockIdx.y * BH;
    const int tx = threadIdx.x;
    const int ty = threadIdx.y;
    const int tid = ty * TX + tx;

    // Per-block clamped, 16B-aligned load window: 48 floats starting at base_x.
    // Covers [x0-2, x0+33] (all taps) for every block; x-clamp shifts only feed
    // the forced-zero border. Value at global x g lands at smem col g-base_x+4.
    int base_x = x0 - 8;
    if (base_x < 0) base_x = 0;
    if (base_x > IMG_W - 48) base_x = IMG_W - 48;   // 208

    for (int idx = tid; idx < NLOAD; idx += TX * TYB) {
        int ly = idx / NF4;
        int lf = idx - ly * NF4;
        int gy = min(max(y0 + ly - 2, 0), IMG_H - 1);   // clamped rows feed zeros
        float4 v = *reinterpret_cast<const float4*>(im + gy * IMG_W + base_x + lf * 4);
        *reinterpret_cast<float4*>(&tile[ly][4 + lf * 4]) = v;
    }
    __syncthreads();

    // Tap at (gy+di, gx+dj), j = dj+2: smem col = tx + j + xoff.
    const int xoff = x0 - base_x + 2;
    const int rbase = ty * PY;

    float nc2[PY];   // -2 * center
    float acc[PY];   // 2 * running sum (center tap pre-seeded: w == 1)
    #pragma unroll
    for (int k = 0; k < PY; k++) {
        nc2[k] = -2.0f * tile[rbase + k + 2][tx + 2 + xoff];
        acc[k] = 2.0f;
    }

    // Slide over the PY+4 tap rows; each row's 5 values feed up to 5 outputs.
    #pragma unroll
    for (int ry = 0; ry < PY + 4; ry++) {
        float a[5];
        #pragma unroll
        for (int j = 0; j < 5; j++) a[j] = tile[rbase + ry][tx + j + xoff];

        #pragma unroll
        for (int k = 0; k < PY; k++) {
            if (ry >= k && ry <= k + 4) {
                #pragma unroll
                for (int j = 0; j < 5; j++) {
                    if (ry == k + 2 && j == 2) continue;   // center: skipped
                    float d = fmaf(a[j], 2.0f, nc2[k]);        // 2(a - c), FFMA-imm
                    float w = fmaxf(1.0f - fabsf(d), 0.0f);    // FADD(-|d|) + FMNMX
                    acc[k] = fmaf(w, 2.0f, acc[k]);            // FFMA-imm
                }
            }
        }
    }

    const int gx = x0 + tx;
    const bool xin = (gx >= 2) && (gx < IMG_W - 2);
    #pragma unroll
    for (int k = 0; k < PY; k++) {
        int gy = y0 + rbase + k;
        bool yin = (gy >= 2) && (gy < IMG_H - 2);
        om[gy * IMG_W + gx] = (xin && yin) ? 0.5f * acc[k] : 0.0f;
    }
}

extern "C" void kernel_launch(void* const* d_in, const int* in_sizes, int n_in,
                              void* d_out, int out_size) {
    const float* in = (const float*)d_in[0];
    float* out = (float*)d_out;
    dim3 block(TX, TYB, 1);
    dim3 grid(IMG_W / TX, IMG_H / BH, 96);   // 8 x 4 x 96 = 3072 blocks
    soft_hist_kernel<<<grid, block>>>(in, out);
}

// round 5
// speedup vs baseline: 1.7202x; 1.2129x over previous
#include <cuda_runtime.h>
#include <cuda_bf16.h>

// Soft local histogram, R=5, bandwidth=0.5.
// Input/output: (4, 8, 3, 256, 256) fp32 -> 96 images of 256x256.
// out[y,x] = sum_{di,dj in [-2,2]} max(0, 1 - 2*|x[y+di,x+dj] - x[y,x]|)
// for y,x in [2, 254); zero on the 2-pixel border.
//
// Tap math is three FFMA-imm (rt=1) instructions, no alu-pipe ops:
//   d   = fmaf(a, 2.0f, -2c)                    // FFMA-imm
//   w   = __saturatef(fmaf(|d|, -1.0f, 1.0f))   // FFMA.SAT with |src|; since
//         1-|d| <= 1, sat == relu exactly.
//   acc = fmaf(w, 2.0f, acc)                    // FFMA-imm; acc = 2*sum
// Center tap (w == 1) skipped; acc seeded with 2.0.

#define IMG_H 256
#define IMG_W 256
#define TX 32
#define TYB 8
#define PY 8
#define BH (TYB * PY)          // 64 output rows per block
#define TILE_H (BH + 4)        // 68
#define TILE_W 56              // padded row width in floats
#define NF4 12                 // float4s loaded per row (48 floats)
#define NLOAD (TILE_H * NF4)   // 816

__global__ __launch_bounds__(TX * TYB, 5) void soft_hist_kernel(
    const float* __restrict__ in, float* __restrict__ out)
{
    __shared__ float tile[TILE_H][TILE_W];

    const int img = blockIdx.z;
    const float* im = in + (size_t)img * IMG_H * IMG_W;
    float* om = out + (size_t)img * IMG_H * IMG_W;

    const int x0 = blockIdx.x * TX;
    const int y0 = blockIdx.y * BH;
    const int tx = threadIdx.x;
    const int ty = threadIdx.y;
    const int tid = ty * TX + tx;

    // Per-block clamped, 16B-aligned load window: 48 floats from base_x.
    // Covers [x0-2, x0+33]; x-clamp shifts only feed the forced-zero border.
    int base_x = x0 - 8;
    if (base_x < 0) base_x = 0;
    if (base_x > IMG_W - 48) base_x = IMG_W - 48;   // 208

    for (int idx = tid; idx < NLOAD; idx += TX * TYB) {
        int ly = idx / NF4;
        int lf = idx - ly * NF4;
        int gy = min(max(y0 + ly - 2, 0), IMG_H - 1);   // clamped rows feed zeros
        float4 v = *reinterpret_cast<const float4*>(im + gy * IMG_W + base_x + lf * 4);
        *reinterpret_cast<float4*>(&tile[ly][4 + lf * 4]) = v;
    }
    __syncthreads();

    const int xoff = x0 - base_x + 2;
    const int rbase = ty * PY;
    const float one = 1.0f;

    float nc2[PY];   // -2 * center
    float acc[PY];   // 2 * running sum (center tap pre-seeded: w == 1)
    #pragma unroll
    for (int k = 0; k < PY; k++) {
        nc2[k] = -2.0f * tile[rbase + k + 2][tx + 2 + xoff];
        acc[k] = 2.0f;
    }

    // Slide over the PY+4 tap rows; each row's 5 values feed up to 5 outputs.
    #pragma unroll
    for (int ry = 0; ry < PY + 4; ry++) {
        float a[5];
        #pragma unroll
        for (int j = 0; j < 5; j++) a[j] = tile[rbase + ry][tx + j + xoff];

        #pragma unroll
        for (int k = 0; k < PY; k++) {
            if (ry >= k && ry <= k + 4) {
                #pragma unroll
                for (int j = 0; j < 5; j++) {
                    if (ry == k + 2 && j == 2) continue;   // center: skipped
                    float d = fmaf(a[j], 2.0f, nc2[k]);                  // FFMA-imm
                    float w = __saturatef(fmaf(fabsf(d), -1.0f, one));   // FFMA.SAT
                    acc[k] = fmaf(w, 2.0f, acc[k]);                      // FFMA-imm
                }
            }
        }
    }

    const int gx = x0 + tx;
    const bool xin = (gx >= 2) && (gx < IMG_W - 2);
    #pragma unroll
    for (int k = 0; k < PY; k++) {
        int gy = y0 + rbase + k;
        bool yin = (gy >= 2) && (gy < IMG_H - 2);
        om[gy * IMG_W + gx] = (xin && yin) ? 0.5f * acc[k] : 0.0f;
    }
}

extern "C" void kernel_launch(void* const* d_in, const int* in_sizes, int n_in,
                              void* d_out, int out_size) {
    const float* in = (const float*)d_in[0];
    float* out = (float*)d_out;
    dim3 block(TX, TYB, 1);
    dim3 grid(IMG_W / TX, IMG_H / BH, 96);   // 8 x 4 x 96 = 3072 blocks
    soft_hist_kernel<<<grid, block>>>(in, out);
}